// round 8
// baseline (speedup 1.0000x reference)
#include <cuda_runtime.h>

// DecisionGate: g = 1/(1+|x|^4); mask = g>=0.5; dispatched[b,p,:] = (mask? g:0)*act[b,:]
// x [4096,64] f32, act [4096,512] f32. Output f32: g [B*P] | mask [B*P] | dispatched [B*P*D]
//
// R8: identical structure to R7 (the measured roofline kernel), with the one
// untested store-policy cell: DEFAULT cache operator on the dispatched stream
// (vs .cs in R7, .wt in R3). Closes the policy matrix.

#define B_DIM 4096
#define P_DIM 64
#define D_DIM 512
#define BP    (B_DIM * P_DIM)

__global__ __launch_bounds__(128, 16)
void decision_gate_kernel(const float* __restrict__ x,
                          const float* __restrict__ act,
                          float* __restrict__ out) {
    const int b = blockIdx.x;
    const int t = threadIdx.x;            // 0..127, one float4 of D=512 each

    // Each thread owns one float4 of act[b] for the whole CTA lifetime.
    const float4 v = reinterpret_cast<const float4*>(act + (size_t)b * D_DIM)[t];

    // Threads 0..63 compute the 64 gate values; emit g and mask; stash w in smem.
    __shared__ float wsm[P_DIM];
    if (t < P_DIM) {
        const float xv = x[b * P_DIM + t];
        const float x2 = xv * xv;
        const float g  = 1.0f / (1.0f + x2 * x2);
        const bool  m  = (g >= 0.5f);
        out[b * P_DIM + t]      = g;
        out[BP + b * P_DIM + t] = m ? 1.0f : 0.0f;
        wsm[t] = m ? g : 0.0f;
    }
    __syncthreads();

    // 64 independent stores per thread (default policy): dispatched[b,p,:] = w[p] * v
    float4* __restrict__ base =
        reinterpret_cast<float4*>(out + (size_t)2 * BP + (size_t)b * P_DIM * D_DIM) + t;

    #pragma unroll
    for (int p = 0; p < P_DIM; p++) {
        const float w = wsm[p];           // broadcast LDS, conflict-free
        float4 r;
        r.x = v.x * w;
        r.y = v.y * w;
        r.z = v.z * w;
        r.w = v.w * w;
        base[(size_t)p * (D_DIM / 4)] = r;
    }
}

extern "C" void kernel_launch(void* const* d_in, const int* in_sizes, int n_in,
                              void* d_out, int out_size) {
    const float* x   = (const float*)d_in[0];   // [4096, 64]
    const float* act = (const float*)d_in[1];   // [4096, 512]
    float* out = (float*)d_out;

    decision_gate_kernel<<<B_DIM, 128>>>(x, act, out);
}

// round 9
// speedup vs baseline: 1.0561x; 1.0561x over previous
#include <cuda_runtime.h>

// DecisionGate: g = 1/(1+|x|^4); mask = g>=0.5; dispatched[b,p,:] = (mask? g:0)*act[b,:]
// x [4096,64] f32, act [4096,512] f32. Output f32: g [B*P] | mask [B*P] | dispatched [B*P*D]
//
// FINAL (R7 form, re-confirmed through R8): 1 batch row per 128-thread CTA;
// act row held in registers (one float4/thread); 64 gate values in smem;
// 64 independent .cs streaming STG.128 per thread.
//
// Measured at the external write-stream roofline (~6.4 TB/s effective for the
// 515 MB dispatched tensor). Eliminated by experiment: .wt and default store
// policy (R3/R8), 2-row CTAs (R4), persistent+prefetch (R5, regression from
// occupancy loss), L2 de-phasing rotation (R6).

#define B_DIM 4096
#define P_DIM 64
#define D_DIM 512
#define BP    (B_DIM * P_DIM)

__global__ __launch_bounds__(128, 16)
void decision_gate_kernel(const float* __restrict__ x,
                          const float* __restrict__ act,
                          float* __restrict__ out) {
    const int b = blockIdx.x;
    const int t = threadIdx.x;            // 0..127, one float4 of D=512 each

    // Each thread owns one float4 of act[b] for the whole CTA lifetime.
    const float4 v = reinterpret_cast<const float4*>(act + (size_t)b * D_DIM)[t];

    // Threads 0..63 compute the 64 gate values; emit g and mask; stash w in smem.
    __shared__ float wsm[P_DIM];
    if (t < P_DIM) {
        const float xv = x[b * P_DIM + t];
        const float x2 = xv * xv;
        const float g  = 1.0f / (1.0f + x2 * x2);
        const bool  m  = (g >= 0.5f);
        __stcs(&out[b * P_DIM + t], g);
        __stcs(&out[BP + b * P_DIM + t], m ? 1.0f : 0.0f);
        wsm[t] = m ? g : 0.0f;
    }
    __syncthreads();

    // 64 independent streaming stores per thread: dispatched[b,p,:] = w[p] * v
    float4* __restrict__ base =
        reinterpret_cast<float4*>(out + (size_t)2 * BP + (size_t)b * P_DIM * D_DIM) + t;

    #pragma unroll
    for (int p = 0; p < P_DIM; p++) {
        const float w = wsm[p];           // broadcast LDS, conflict-free
        float4 r;
        r.x = v.x * w;
        r.y = v.y * w;
        r.z = v.z * w;
        r.w = v.w * w;
        __stcs(base + (size_t)p * (D_DIM / 4), r);
    }
}

extern "C" void kernel_launch(void* const* d_in, const int* in_sizes, int n_in,
                              void* d_out, int out_size) {
    const float* x   = (const float*)d_in[0];   // [4096, 64]
    const float* act = (const float*)d_in[1];   // [4096, 512]
    float* out = (float*)d_out;

    decision_gate_kernel<<<B_DIM, 128>>>(x, act, out);
}